// round 2
// baseline (speedup 1.0000x reference)
#include <cuda_runtime.h>

// SNN XOR net, issue/pipe-bound optimization round.
// Key changes vs R1 kernel:
//  - spike kept as float sneg in {-1,0}: one FSETP+SEL feeds BOTH the next-step
//    reset (m + sneg, exact) and the output-layer accumulation
//    (fmaf(sneg, -w2, acc) == acc + w2 exactly when sneg=-1, acc when 0).
//  - membrane update uses Blackwell packed f32x2 fma/add (bit-identical per lane)
//    to halve fma-pipe instruction count.
//  - arithmetic order identical to the previous passing kernel (no reassociation).

#define T_STEPS 20
#define BETA 0.9f
#define THR 1.0f

__device__ __forceinline__ unsigned long long pack2(float a, float b) {
    unsigned long long r;
    asm("mov.b64 %0, {%1, %2};" : "=l"(r) : "f"(a), "f"(b));
    return r;
}
__device__ __forceinline__ void unpack2(unsigned long long v, float& a, float& b) {
    asm("mov.b64 {%0, %1}, %2;" : "=f"(a), "=f"(b) : "l"(v));
}
__device__ __forceinline__ unsigned long long fma2(unsigned long long a,
                                                   unsigned long long b,
                                                   unsigned long long c) {
    unsigned long long d;
    asm("fma.rn.f32x2 %0, %1, %2, %3;" : "=l"(d) : "l"(a), "l"(b), "l"(c));
    return d;
}
__device__ __forceinline__ unsigned long long add2(unsigned long long a,
                                                   unsigned long long b) {
    unsigned long long d;
    asm("add.rn.f32x2 %0, %1, %2;" : "=l"(d) : "l"(a), "l"(b));
    return d;
}

__global__ void __launch_bounds__(256) snn_xornet_kernel(
    const float* __restrict__ x,    // [B,2]
    const float* __restrict__ w1,   // [4,2]
    const float* __restrict__ w2,   // [1,4]
    float* __restrict__ out,        // [T,B]
    int B)
{
    const int i = blockIdx.x * blockDim.x + threadIdx.x;  // group of 4 elems
    if (i * 4 >= B) return;

    // Broadcast weights (L1 hit after first warp)
    float w1r[4][2];
#pragma unroll
    for (int h = 0; h < 4; h++) {
        w1r[h][0] = __ldg(&w1[2 * h + 0]);
        w1r[h][1] = __ldg(&w1[2 * h + 1]);
    }
    float w2n[4];
#pragma unroll
    for (int h = 0; h < 4; h++) w2n[h] = -__ldg(&w2[h]);   // negated for sneg*(-w2)

    // x for 4 batch elements
    const float4 xa = reinterpret_cast<const float4*>(x)[2 * i + 0];
    const float4 xb = reinterpret_cast<const float4*>(x)[2 * i + 1];
    const float xs[4][2] = {{xa.x, xa.y}, {xa.z, xa.w}, {xb.x, xb.y}, {xb.z, xb.w}};

    // cur = x @ w1^T (same rounding as previous passing kernel), packed in pairs
    unsigned long long curp[4][2];
#pragma unroll
    for (int j = 0; j < 4; j++) {
        float c[4];
#pragma unroll
        for (int h = 0; h < 4; h++)
            c[h] = fmaf(xs[j][0], w1r[h][0], xs[j][1] * w1r[h][1]);
        curp[j][0] = pack2(c[0], c[1]);
        curp[j][1] = pack2(c[2], c[3]);
    }

    const unsigned long long beta2 = pack2(BETA, BETA);

    // State: packed membranes, packed sneg (-1 if spiked last step else 0)
    unsigned long long mp[4][2], snp[4][2];
    float m2[4], s2n[4];
#pragma unroll
    for (int j = 0; j < 4; j++) {
        mp[j][0] = 0ull; mp[j][1] = 0ull;
        snp[j][0] = 0ull; snp[j][1] = 0ull;
        m2[j] = 0.0f; s2n[j] = 0.0f;
    }

    float4* out4 = reinterpret_cast<float4*>(out);
    const int Bq = B >> 2;

#pragma unroll 4
    for (int t = 0; t < T_STEPS; t++) {
        float o[4];
#pragma unroll
        for (int j = 0; j < 4; j++) {
            // m = fma(beta, m, cur) + sneg_old   (bit-identical to fma then -reset)
            mp[j][0] = add2(fma2(beta2, mp[j][0], curp[j][0]), snp[j][0]);
            mp[j][1] = add2(fma2(beta2, mp[j][1], curp[j][1]), snp[j][1]);

            float m0, m1, mh2, mh3;
            unpack2(mp[j][0], m0, m1);
            unpack2(mp[j][1], mh2, mh3);

            const float s0 = (m0  > THR) ? -1.0f : 0.0f;
            const float s1 = (m1  > THR) ? -1.0f : 0.0f;
            const float s2 = (mh2 > THR) ? -1.0f : 0.0f;
            const float s3 = (mh3 > THR) ? -1.0f : 0.0f;

            // acc accumulated in the same h0..h3 order as before:
            // fmaf(-1, -w2, acc) rounds once == acc + w2 exactly.
            float acc = fmaf(s0, w2n[0], 0.0f);
            acc = fmaf(s1, w2n[1], acc);
            acc = fmaf(s2, w2n[2], acc);
            acc = fmaf(s3, w2n[3], acc);

            snp[j][0] = pack2(s0, s1);
            snp[j][1] = pack2(s2, s3);

            // output neuron
            m2[j] = fmaf(BETA, m2[j], acc) + s2n[j];
            const bool p2 = m2[j] > THR;
            s2n[j] = p2 ? -1.0f : 0.0f;
            o[j]   = p2 ?  1.0f : 0.0f;
        }
        float4 v;
        v.x = o[0]; v.y = o[1]; v.z = o[2]; v.w = o[3];
        out4[(size_t)t * Bq + i] = v;
    }
}

extern "C" void kernel_launch(void* const* d_in, const int* in_sizes, int n_in,
                              void* d_out, int out_size) {
    const float* x  = (const float*)d_in[0];   // [B,2]
    const float* w1 = (const float*)d_in[1];   // [4,2]
    const float* w2 = (const float*)d_in[2];   // [1,4]
    float* out = (float*)d_out;                // [T,B,1]

    const int B = in_sizes[0] / 2;
    const int groups = B / 4;
    const int threads = 256;
    const int blocks = (groups + threads - 1) / threads;
    snn_xornet_kernel<<<blocks, threads>>>(x, w1, w2, out, B);
}